// round 12
// baseline (speedup 1.0000x reference)
#include <cuda_runtime.h>
#include <cstdint>

// TransitionGNN via legacy mma.sync.m16n8k8 TF32 (single pass).
// R12: W tile double-buffered at k-chunk granularity (phase A: si x W[k0:64) while
// W[k64:128) loads; phase B: sj x W[k64:128) while next edge's chunk loads).
// Bias folded into epilogue from gmem. 2 CTAs/SM (TB=64, 256 thr, 2m x 4n).
// B=8192, K=10, D=64, H=128, A=16, E=90, F=208.

#define KN 10
#define TB 64
#define NT 256

// padded row strides (bytes); (stride/16) mod 8 coprime-ish -> ldmatrix conflict-free
#define S_S   272   // states rows: 256B + 16
#define S_A   80    // action rows: 64B + 16
#define S_WC  272   // W^T k-chunk rows: 64k*4B + 16
#define S_AG  528   // agg rows: 128*4B + 16
#define S_WNA 464   // Wn^T chunkA rows: 112*4B + 16
#define S_WNB 400   // Wn^T chunkB rows: 96*4B + 16

#define WCHUNK (128 * S_WC)   // 34816 bytes per W k-chunk

// ---- staged scratch (tf32, pre-padded rows) ----
__device__ __align__(16) unsigned char g_s[KN * 8192 * S_S];       // [j][b][64k]
__device__ __align__(16) unsigned char g_a[KN * 8192 * S_A];       // [j][b][16a]
__device__ __align__(16) unsigned char g_We[90 * 2 * WCHUNK];      // W^T [e][c][128h][64k]
__device__ __align__(16) unsigned char g_WnA[KN * 64 * S_WNA];     // Wn^T [i][64d][f0..111]
__device__ __align__(16) unsigned char g_WnB[KN * 64 * S_WNB];     // Wn^T [i][64d][f112..207]

// ---- smem map (bytes), per CTA 109568 => 2 CTAs/SM ----
#define SI    0u                    // 17408
#define SJ    17408u                // 17408
#define ACT   34816u                // 5120
#define WB0   39936u                // 34816 (W chunk ping)
#define WB1   74752u                // 34816 (W chunk pong)
#define SMEM_TOTAL 109568
// node-phase aliases:
#define AGG   (WB1)                 // 64 x 528 = 33792
#define WN    (WB0)                 // <= 29696

__device__ __forceinline__ uint32_t tf32c(float x) {
    uint32_t r; asm("cvt.rna.tf32.f32 %0, %1;" : "=r"(r) : "f"(x)); return r;
}
__device__ __forceinline__ float tanha(float x) {
    float r; asm("tanh.approx.f32 %0, %1;" : "=f"(r) : "f"(x)); return r;
}
__device__ __forceinline__ void cp16(uint32_t s, const void* g) {
    asm volatile("cp.async.cg.shared.global [%0], [%1], 16;" :: "r"(s), "l"(g));
}
__device__ __forceinline__ void cpblk(uint32_t sdst, const void* gsrc, int bytes, int tid) {
    for (int off = tid * 16; off < bytes; off += NT * 16)
        cp16(sdst + off, (const char*)gsrc + off);
}
#define CP_COMMIT() asm volatile("cp.async.commit_group;")
#define CP_WAIT(n)  asm volatile("cp.async.wait_group %0;" :: "n"(n))

__device__ __forceinline__ void ldsm4(uint32_t a, uint32_t r[4]) {
    asm volatile("ldmatrix.sync.aligned.m8n8.x4.shared.b16 {%0,%1,%2,%3}, [%4];"
        : "=r"(r[0]), "=r"(r[1]), "=r"(r[2]), "=r"(r[3]) : "r"(a));
}
__device__ __forceinline__ void mma8(float c[4], const uint32_t a[4], uint32_t b0, uint32_t b1) {
    asm volatile("mma.sync.aligned.m16n8k8.row.col.f32.tf32.tf32.f32 "
        "{%0,%1,%2,%3},{%4,%5,%6,%7},{%8,%9},{%0,%1,%2,%3};"
        : "+f"(c[0]), "+f"(c[1]), "+f"(c[2]), "+f"(c[3])
        : "r"(a[0]), "r"(a[1]), "r"(a[2]), "r"(a[3]), "r"(b0), "r"(b1));
}
// A-tile lane base (m16 x k8 x4-ldmatrix); addr(ks) = base + ks*32
__device__ __forceinline__ uint32_t baseA(uint32_t buf, int r0, int S, int lane) {
    int row = r0 + (lane & 7) + ((lane >> 3) & 1) * 8;
    return buf + (uint32_t)(row * S) + ((uint32_t)(lane >> 4) << 4);
}
// B-tile lane base (n16 x k8 x4-ldmatrix from W^T rows=n); addr(ks) = base + ks*32
__device__ __forceinline__ uint32_t baseB(uint32_t buf, int r0, int S, int lane) {
    int row = r0 + (lane & 7) + ((lane >> 4) << 3);
    return buf + (uint32_t)(row * S) + ((uint32_t)((lane >> 3) & 1) << 4);
}

// ===================== prep kernel =====================
__global__ void prep_kernel(const float* __restrict__ states, const float* __restrict__ action,
                            const float* __restrict__ Wed, const float* __restrict__ Wn)
{
    int tid = blockIdx.x * blockDim.x + threadIdx.x;
    int NTH = gridDim.x * blockDim.x;
    // states
    for (int p = tid; p < KN * 8192 * 32; p += NTH) {
        int d2 = p & 31, b = (p >> 5) & 8191, j = p >> 18;
        float2 v = *(const float2*)&states[((size_t)b * KN + j) * 64 + 2 * d2];
        uint2 w = { tf32c(v.x), tf32c(v.y) };
        *(uint2*)(g_s + (size_t)(j * 8192 + b) * S_S + d2 * 8) = w;
    }
    // action
    for (int p = tid; p < KN * 8192 * 8; p += NTH) {
        int a2 = p & 7, b = (p >> 3) & 8191, j = p >> 16;
        float2 v = *(const float2*)&action[((size_t)b * KN + j) * 16 + 2 * a2];
        uint2 w = { tf32c(v.x), tf32c(v.y) };
        *(uint2*)(g_a + (size_t)(j * 8192 + b) * S_A + a2 * 8) = w;
    }
    // W_edge [e][k][h] -> W^T in k-chunks: [(e*2+c)][h][kc]
    for (int p = tid; p < 90 * 128 * 64; p += NTH) {
        int h2 = p & 63, k = (p >> 6) & 127, e = p >> 13;
        float2 v = *(const float2*)&Wed[((size_t)e * 128 + k) * 128 + 2 * h2];
        int c = k >> 6, kc = k & 63;
        int h0 = 2 * h2;
        size_t base = (size_t)(e * 2 + c) * WCHUNK;
        *(uint32_t*)(g_We + base + (size_t)h0       * S_WC + kc * 4) = tf32c(v.x);
        *(uint32_t*)(g_We + base + (size_t)(h0 + 1) * S_WC + kc * 4) = tf32c(v.y);
    }
    // W_node [i][f][d] -> Wn^T rows d; f split at 112
    for (int p = tid; p < KN * 208 * 32; p += NTH) {
        int d2 = p & 31, fi = p >> 5;
        int f = fi % 208, i = fi / 208;
        float2 v = *(const float2*)&Wn[((size_t)i * 208 + f) * 64 + 2 * d2];
        int d0 = 2 * d2;
        if (f < 112) {
            unsigned char* base = g_WnA + (size_t)i * (64 * S_WNA);
            *(uint32_t*)(base + (size_t)d0       * S_WNA + f * 4) = tf32c(v.x);
            *(uint32_t*)(base + (size_t)(d0 + 1) * S_WNA + f * 4) = tf32c(v.y);
        } else {
            unsigned char* base = g_WnB + (size_t)i * (64 * S_WNB);
            int fc = f - 112;
            *(uint32_t*)(base + (size_t)d0       * S_WNB + fc * 4) = tf32c(v.x);
            *(uint32_t*)(base + (size_t)(d0 + 1) * S_WNB + fc * 4) = tf32c(v.y);
        }
    }
}

// ===================== main kernel =====================
extern "C" __global__ void __launch_bounds__(NT, 2)
gnn_tf32_kernel(const float* __restrict__ b_edge,   // [E,H]
                const float* __restrict__ b_node,   // [K,D]
                float* __restrict__ out)            // [B,K,D]
{
    extern __shared__ char smem[];
    const uint32_t sb = (uint32_t)__cvta_generic_to_shared(smem);

    const int i    = blockIdx.y;
    const int b0   = blockIdx.x * TB;
    const int tid  = threadIdx.x;
    const int lane = tid & 31;
    const int wid  = tid >> 5;
    const int wm   = wid & 1;    // 2 m-warps: rows 32*wm .. +31
    const int wn   = wid >> 1;   // 4 n-warps: edge cols 32*wn, node cols 16*wn
    const int m0   = 32 * wm;

    // ---- prologue: G_a{si, act, sj0, Wc0(e0)}, G_b{Wc1(e0)} ----
    cpblk(sb + SI,  g_s + (size_t)(i * 8192 + b0) * S_S, TB * S_S, tid);
    cpblk(sb + ACT, g_a + (size_t)(i * 8192 + b0) * S_A, TB * S_A, tid);
    {
        int j0 = (i == 0) ? 1 : 0;
        cpblk(sb + SJ,  g_s + (size_t)(j0 * 8192 + b0) * S_S, TB * S_S, tid);
        cpblk(sb + WB0, g_We + (size_t)(i * 9) * 2 * WCHUNK, WCHUNK, tid);
    }
    CP_COMMIT();
    cpblk(sb + WB1, g_We + ((size_t)(i * 9) * 2 + 1) * WCHUNK, WCHUNK, tid);
    CP_COMMIT();

    // lane bases (loop-invariant)
    const uint32_t aSI0 = baseA(sb + SI, m0,      S_S, lane);
    const uint32_t aSI1 = baseA(sb + SI, m0 + 16, S_S, lane);
    const uint32_t aSJ0 = baseA(sb + SJ, m0,      S_S, lane);
    const uint32_t aSJ1 = baseA(sb + SJ, m0 + 16, S_S, lane);
    const uint32_t b0A  = baseB(sb + WB0, 32 * wn,      S_WC, lane);
    const uint32_t b0B  = baseB(sb + WB0, 32 * wn + 16, S_WC, lane);
    const uint32_t b1A  = baseB(sb + WB1, 32 * wn,      S_WC, lane);
    const uint32_t b1B  = baseB(sb + WB1, 32 * wn + 16, S_WC, lane);

    float C[32], agg[32];
    #pragma unroll
    for (int q = 0; q < 32; ++q) agg[q] = 0.0f;

    // ---- edge loop (software-pipelined at k-chunk granularity) ----
    #pragma unroll
    for (int t = 0; t < 9; ++t) {
        const int e = i * 9 + t;

        // bias for this edge (L2-hot LDG; consumed only in epilogue)
        float2 bv[4];
        #pragma unroll
        for (int p = 0; p < 4; ++p)
            bv[p] = *(const float2*)&b_edge[(size_t)e * 128 + 32 * wn + 8 * p + (lane & 3) * 2];

        #pragma unroll
        for (int q = 0; q < 32; ++q) C[q] = 0.0f;

        // --- phase A: si x Wc0 (buf0), ks 0..7 ---
        CP_WAIT(1);          // Wc0_t complete (issued a full phase ago)
        __syncthreads();
        #pragma unroll
        for (int ks = 0; ks < 8; ++ks) {
            const uint32_t koff = (uint32_t)(ks * 32);
            uint32_t a0[4], a1[4], bA[4], bB[4];
            ldsm4(aSI0 + koff, a0);
            ldsm4(aSI1 + koff, a1);
            ldsm4(b0A + koff, bA);
            ldsm4(b0B + koff, bB);
            mma8(C + 0,  a0, bA[0], bA[1]);
            mma8(C + 4,  a0, bA[2], bA[3]);
            mma8(C + 8,  a0, bB[0], bB[1]);
            mma8(C + 12, a0, bB[2], bB[3]);
            mma8(C + 16, a1, bA[0], bA[1]);
            mma8(C + 20, a1, bA[2], bA[3]);
            mma8(C + 24, a1, bB[0], bB[1]);
            mma8(C + 28, a1, bB[2], bB[3]);
        }
        __syncthreads();     // buf0 consumed
        if (t < 8)
            cpblk(sb + WB0, g_We + (size_t)(e + 1) * 2 * WCHUNK, WCHUNK, tid);
        else
            cpblk(sb + WN, g_WnA + (size_t)i * (64 * S_WNA), 64 * S_WNA, tid);  // WN==WB0
        CP_COMMIT();

        // --- phase B: sj x Wc1 (buf1), ks 0..7 ---
        CP_WAIT(1);          // Wc1_t + sj_t complete
        __syncthreads();
        #pragma unroll
        for (int ks = 0; ks < 8; ++ks) {
            const uint32_t koff = (uint32_t)(ks * 32);
            uint32_t a0[4], a1[4], bA[4], bB[4];
            ldsm4(aSJ0 + koff, a0);
            ldsm4(aSJ1 + koff, a1);
            ldsm4(b1A + koff, bA);
            ldsm4(b1B + koff, bB);
            mma8(C + 0,  a0, bA[0], bA[1]);
            mma8(C + 4,  a0, bA[2], bA[3]);
            mma8(C + 8,  a0, bB[0], bB[1]);
            mma8(C + 12, a0, bB[2], bB[3]);
            mma8(C + 16, a1, bA[0], bA[1]);
            mma8(C + 20, a1, bA[2], bA[3]);
            mma8(C + 24, a1, bB[0], bB[1]);
            mma8(C + 28, a1, bB[2], bB[3]);
        }
        __syncthreads();     // buf1 + sj consumed
        if (t < 8) {
            int jn = (t + 1) + ((t + 1) >= i ? 1 : 0);
            cpblk(sb + SJ,  g_s + (size_t)(jn * 8192 + b0) * S_S, TB * S_S, tid);
            cpblk(sb + WB1, g_We + ((size_t)(e + 1) * 2 + 1) * WCHUNK, WCHUNK, tid);
        }
        CP_COMMIT();         // (empty at t==8 is fine)

        // --- epilogue: agg += tanh(C + bias); overlaps in-flight loads ---
        #pragma unroll
        for (int m = 0; m < 2; ++m)
            #pragma unroll
            for (int p = 0; p < 4; ++p) {
                float* c = C + m * 16 + p * 4;
                float* g = agg + m * 16 + p * 4;
                g[0] += tanha(c[0] + bv[p].x);
                g[1] += tanha(c[1] + bv[p].y);
                g[2] += tanha(c[2] + bv[p].x);
                g[3] += tanha(c[3] + bv[p].y);
            }
    }

    // ---- node phase: write agg as tf32 A-tile [64r][128h] into AGG (buf1) ----
    #pragma unroll
    for (int m = 0; m < 2; ++m)
        #pragma unroll
        for (int p = 0; p < 4; ++p) {
            int h = 32 * wn + 8 * p + (lane & 3) * 2;
            int idx = m * 16 + p * 4;
            #pragma unroll
            for (int hh = 0; hh < 2; ++hh) {
                int r = m0 + m * 16 + (lane >> 2) + 8 * hh;
                uint2 w = { tf32c(agg[idx + 2 * hh]), tf32c(agg[idx + 2 * hh + 1]) };
                *(uint2*)(smem + AGG + (uint32_t)(r * S_AG) + (uint32_t)(h * 4)) = w;
            }
        }
    CP_WAIT(0);          // WnA staged (issued after phase A of edge 8)
    __syncthreads();     // + AGG visible

    // node lane bases
    const uint32_t aACT0 = baseA(sb + ACT, m0,      S_A, lane);
    const uint32_t aACT1 = baseA(sb + ACT, m0 + 16, S_A, lane);
    const uint32_t aAG0  = baseA(sb + AGG, m0,      S_AG, lane);
    const uint32_t aAG1  = baseA(sb + AGG, m0 + 16, S_AG, lane);

    // init C2 from node bias
    float C2[16];
    #pragma unroll
    for (int p = 0; p < 2; ++p) {
        int d = 16 * wn + 8 * p + (lane & 3) * 2;
        float2 bn = *(const float2*)&b_node[(size_t)i * 64 + d];
        #pragma unroll
        for (int m = 0; m < 2; ++m) {
            float* c = C2 + m * 8 + p * 4;
            c[0] = bn.x; c[1] = bn.y; c[2] = bn.x; c[3] = bn.y;
        }
    }

    // node GEMM: 26 k8-steps over F=208; WN chunkA = ks 0..13, chunkB = ks 14..25
    #pragma unroll
    for (int chunk = 0; chunk < 2; ++chunk) {
        const int S_WN = chunk ? S_WNB : S_WNA;
        const uint32_t bWN = baseB(sb + WN, 16 * wn, S_WN, lane);
        const int ksBeg = chunk ? 14 : 0;
        const int ksEnd = chunk ? 26 : 14;
        #pragma unroll
        for (int ks = ksBeg; ks < ksEnd; ++ks) {
            uint32_t a0[4], a1[4], bN[4];
            if (ks < 8) {
                ldsm4(aSI0 + (uint32_t)(ks * 32), a0);
                ldsm4(aSI1 + (uint32_t)(ks * 32), a1);
            } else if (ks < 10) {
                ldsm4(aACT0 + (uint32_t)((ks - 8) * 32), a0);
                ldsm4(aACT1 + (uint32_t)((ks - 8) * 32), a1);
            } else {
                ldsm4(aAG0 + (uint32_t)((ks - 10) * 32), a0);
                ldsm4(aAG1 + (uint32_t)((ks - 10) * 32), a1);
            }
            ldsm4(bWN + (uint32_t)((ks - ksBeg) * 32), bN);
            mma8(C2 + 0,  a0, bN[0], bN[1]);
            mma8(C2 + 4,  a0, bN[2], bN[3]);
            mma8(C2 + 8,  a1, bN[0], bN[1]);
            mma8(C2 + 12, a1, bN[2], bN[3]);
        }
        if (chunk == 0) {
            __syncthreads();   // WnA fully consumed
            cpblk(sb + WN, g_WnB + (size_t)i * (64 * S_WNB), 64 * S_WNB, tid);
            CP_COMMIT();
            CP_WAIT(0);
            __syncthreads();   // WnB staged
        }
    }

    // ---- final epilogue: tanh + store ----
    #pragma unroll
    for (int m = 0; m < 2; ++m)
        #pragma unroll
        for (int p = 0; p < 2; ++p) {
            int d = 16 * wn + 8 * p + (lane & 3) * 2;
            int r0 = m0 + m * 16 + (lane >> 2);
            const float* c = C2 + m * 8 + p * 4;
            float2 v0 = { tanha(c[0]), tanha(c[1]) };
            float2 v1 = { tanha(c[2]), tanha(c[3]) };
            *(float2*)&out[((size_t)(b0 + r0)     * KN + i) * 64 + d] = v0;
            *(float2*)&out[((size_t)(b0 + r0 + 8) * KN + i) * 64 + d] = v1;
        }
}

extern "C" void kernel_launch(void* const* d_in, const int* in_sizes, int n_in,
                              void* d_out, int out_size)
{
    const float* states = (const float*)d_in[0];
    const float* action = (const float*)d_in[1];
    const float* W_edge = (const float*)d_in[2];
    const float* b_edge = (const float*)d_in[3];
    const float* W_node = (const float*)d_in[4];
    const float* b_node = (const float*)d_in[5];
    float* out = (float*)d_out;

    int B = in_sizes[0] / (KN * 64);   // 8192

    prep_kernel<<<2048, 256>>>(states, action, W_edge, W_node);

    cudaFuncSetAttribute(gnn_tf32_kernel,
                         cudaFuncAttributeMaxDynamicSharedMemorySize, SMEM_TOTAL);
    dim3 grid(B / TB, KN);
    gnn_tf32_kernel<<<grid, NT, SMEM_TOTAL>>>(b_edge, b_node, out);
}

// round 13
// speedup vs baseline: 1.1779x; 1.1779x over previous
#include <cuda_runtime.h>
#include <cstdint>

// TransitionGNN via legacy mma.sync.m16n8k8 TF32 (single pass).
// R13: 4-warp CTAs (128 thr), warp tile M32xN64 (2m x 2n) -> ldsm bytes/MMA
// drops 250->187 (A and B each duplicated only 2x). 2 CTAs/SM, register-free
// (256 regs/thread available). R11 single-W-buffer flow (beat R12's chunking).
// B=8192, K=10, D=64, H=128, A=16, E=90, F=208.

#define KN 10
#define TB 64
#define NT 128

// padded row strides (bytes); (stride/4) mod 32 in {4,20} -> ldmatrix conflict-free
#define S_S   272   // states rows: 256B + 16
#define S_A   80    // action rows: 64B + 16
#define S_W   528   // W^T rows: 512B + 16
#define S_WNA 464   // Wn^T chunkA rows: 448B + 16
#define S_WNB 400   // Wn^T chunkB rows: 384B + 16

// ---- staged scratch (tf32, pre-padded rows) ----
__device__ __align__(16) unsigned char g_s[KN * 8192 * S_S];      // [j][b][64k]
__device__ __align__(16) unsigned char g_a[KN * 8192 * S_A];      // [j][b][16a]
__device__ __align__(16) unsigned char g_We[90 * 128 * S_W];      // W^T [e][128h][128k]
__device__ __align__(16) unsigned char g_WnA[KN * 64 * S_WNA];    // Wn^T [i][64d][f0..111]
__device__ __align__(16) unsigned char g_WnB[KN * 64 * S_WNB];    // Wn^T [i][64d][f112..207]

// ---- smem map (bytes), per CTA 112128 => 2 CTAs/SM ----
#define SI    0u                    // 64 x 272 = 17408
#define SJ    17408u                // 17408
#define ACT   34816u                // 64 x 80 = 5120
#define BIAS  39936u                // 4608 (9 x 512)
#define WE    44544u                // 128 x 528 = 67584
#define SMEM_TOTAL 112128
// node-phase aliases inside WE:
#define AGG   (WE)                  // 64 x 528 = 33792
#define WN    (WE + 33792u)         // <= 29696

__device__ __forceinline__ uint32_t tf32c(float x) {
    uint32_t r; asm("cvt.rna.tf32.f32 %0, %1;" : "=r"(r) : "f"(x)); return r;
}
__device__ __forceinline__ float tanha(float x) {
    float r; asm("tanh.approx.f32 %0, %1;" : "=f"(r) : "f"(x)); return r;
}
__device__ __forceinline__ void cp16(uint32_t s, const void* g) {
    asm volatile("cp.async.cg.shared.global [%0], [%1], 16;" :: "r"(s), "l"(g));
}
__device__ __forceinline__ void cpblk(uint32_t sdst, const void* gsrc, int bytes, int tid) {
    for (int off = tid * 16; off < bytes; off += NT * 16)
        cp16(sdst + off, (const char*)gsrc + off);
}
#define CP_COMMIT() asm volatile("cp.async.commit_group;")
#define CP_WAIT0()  asm volatile("cp.async.wait_group 0;")

__device__ __forceinline__ void ldsm4(uint32_t a, uint32_t r[4]) {
    asm volatile("ldmatrix.sync.aligned.m8n8.x4.shared.b16 {%0,%1,%2,%3}, [%4];"
        : "=r"(r[0]), "=r"(r[1]), "=r"(r[2]), "=r"(r[3]) : "r"(a));
}
__device__ __forceinline__ void mma8(float c[4], const uint32_t a[4], uint32_t b0, uint32_t b1) {
    asm volatile("mma.sync.aligned.m16n8k8.row.col.f32.tf32.tf32.f32 "
        "{%0,%1,%2,%3},{%4,%5,%6,%7},{%8,%9},{%0,%1,%2,%3};"
        : "+f"(c[0]), "+f"(c[1]), "+f"(c[2]), "+f"(c[3])
        : "r"(a[0]), "r"(a[1]), "r"(a[2]), "r"(a[3]), "r"(b0), "r"(b1));
}
// A-tile lane base (m16 x k8 x4-ldmatrix); addr(ks) = base + ks*32
__device__ __forceinline__ uint32_t baseA(uint32_t buf, int r0, int S, int lane) {
    int row = r0 + (lane & 7) + ((lane >> 3) & 1) * 8;
    return buf + (uint32_t)(row * S) + ((uint32_t)(lane >> 4) << 4);
}
// B-tile lane base (n16 x k8 x4-ldmatrix from W^T rows=n); addr(ks) = base + ks*32
__device__ __forceinline__ uint32_t baseB(uint32_t buf, int r0, int S, int lane) {
    int row = r0 + (lane & 7) + ((lane >> 4) << 3);
    return buf + (uint32_t)(row * S) + ((uint32_t)((lane >> 3) & 1) << 4);
}

// ===================== prep kernel =====================
__global__ void prep_kernel(const float* __restrict__ states, const float* __restrict__ action,
                            const float* __restrict__ Wed, const float* __restrict__ Wn)
{
    int tid = blockIdx.x * blockDim.x + threadIdx.x;
    int NTH = gridDim.x * blockDim.x;
    for (int p = tid; p < KN * 8192 * 32; p += NTH) {
        int d2 = p & 31, b = (p >> 5) & 8191, j = p >> 18;
        float2 v = *(const float2*)&states[((size_t)b * KN + j) * 64 + 2 * d2];
        uint2 w = { tf32c(v.x), tf32c(v.y) };
        *(uint2*)(g_s + (size_t)(j * 8192 + b) * S_S + d2 * 8) = w;
    }
    for (int p = tid; p < KN * 8192 * 8; p += NTH) {
        int a2 = p & 7, b = (p >> 3) & 8191, j = p >> 16;
        float2 v = *(const float2*)&action[((size_t)b * KN + j) * 16 + 2 * a2];
        uint2 w = { tf32c(v.x), tf32c(v.y) };
        *(uint2*)(g_a + (size_t)(j * 8192 + b) * S_A + a2 * 8) = w;
    }
    for (int p = tid; p < 90 * 128 * 64; p += NTH) {
        int h2 = p & 63, k = (p >> 6) & 127, e = p >> 13;
        float2 v = *(const float2*)&Wed[((size_t)e * 128 + k) * 128 + 2 * h2];
        int h0 = 2 * h2;
        *(uint32_t*)(g_We + (size_t)(e * 128 + h0)     * S_W + k * 4) = tf32c(v.x);
        *(uint32_t*)(g_We + (size_t)(e * 128 + h0 + 1) * S_W + k * 4) = tf32c(v.y);
    }
    for (int p = tid; p < KN * 208 * 32; p += NTH) {
        int d2 = p & 31, fi = p >> 5;
        int f = fi % 208, i = fi / 208;
        float2 v = *(const float2*)&Wn[((size_t)i * 208 + f) * 64 + 2 * d2];
        int d0 = 2 * d2;
        if (f < 112) {
            unsigned char* base = g_WnA + (size_t)i * (64 * S_WNA);
            *(uint32_t*)(base + (size_t)d0       * S_WNA + f * 4) = tf32c(v.x);
            *(uint32_t*)(base + (size_t)(d0 + 1) * S_WNA + f * 4) = tf32c(v.y);
        } else {
            unsigned char* base = g_WnB + (size_t)i * (64 * S_WNB);
            int fc = f - 112;
            *(uint32_t*)(base + (size_t)d0       * S_WNB + fc * 4) = tf32c(v.x);
            *(uint32_t*)(base + (size_t)(d0 + 1) * S_WNB + fc * 4) = tf32c(v.y);
        }
    }
}

// ===================== main kernel =====================
extern "C" __global__ void __launch_bounds__(NT, 2)
gnn_tf32_kernel(const float* __restrict__ b_edge,   // [E,H]
                const float* __restrict__ b_node,   // [K,D]
                float* __restrict__ out)            // [B,K,D]
{
    extern __shared__ char smem[];
    const uint32_t sb = (uint32_t)__cvta_generic_to_shared(smem);

    const int i    = blockIdx.y;
    const int b0   = blockIdx.x * TB;
    const int tid  = threadIdx.x;
    const int lane = tid & 31;
    const int wid  = tid >> 5;
    const int wm   = wid & 1;    // 2 m-warps: rows 32*wm .. +31
    const int wn   = wid >> 1;   // 2 n-warps: edge cols 64*wn, node cols 32*wn
    const int m0   = 32 * wm;

    // ---- prologue: si, act, bias, sj0, W0 (one group) ----
    cpblk(sb + SI,   g_s + (size_t)(i * 8192 + b0) * S_S, TB * S_S, tid);
    cpblk(sb + ACT,  g_a + (size_t)(i * 8192 + b0) * S_A, TB * S_A, tid);
    cpblk(sb + BIAS, b_edge + (size_t)(i * 9) * 128, 4608, tid);
    {
        int j0 = (i == 0) ? 1 : 0;
        cpblk(sb + SJ, g_s + (size_t)(j0 * 8192 + b0) * S_S, TB * S_S, tid);
        cpblk(sb + WE, g_We + (size_t)(i * 9) * (128 * S_W), 128 * S_W, tid);
    }
    CP_COMMIT();

    // lane bases (loop-invariant)
    const uint32_t aSI0 = baseA(sb + SI, m0,      S_S, lane);
    const uint32_t aSI1 = baseA(sb + SI, m0 + 16, S_S, lane);
    const uint32_t aSJ0 = baseA(sb + SJ, m0,      S_S, lane);
    const uint32_t aSJ1 = baseA(sb + SJ, m0 + 16, S_S, lane);
    uint32_t bWE[4];
    #pragma unroll
    for (int q = 0; q < 4; ++q)
        bWE[q] = baseB(sb + WE, 64 * wn + 16 * q, S_W, lane);

    float C[64], agg[64];
    #pragma unroll
    for (int q = 0; q < 64; ++q) agg[q] = 0.0f;

    // ---- edge loop ----
    #pragma unroll
    for (int t = 0; t < 9; ++t) {
        CP_WAIT0();
        __syncthreads();     // W_t, sj_t (t==0: +si/act/bias) visible

        // init C from bias: C[m*32 + q*8 + half*4 + e], col h = 64*wn+16q+8*half+2*(lane&3)
        {
            const float* bs = (const float*)(smem + BIAS) + t * 128;
            #pragma unroll
            for (int q = 0; q < 4; ++q)
                #pragma unroll
                for (int hf = 0; hf < 2; ++hf) {
                    int h = 64 * wn + 16 * q + 8 * hf + (lane & 3) * 2;
                    float2 bv = *(const float2*)&bs[h];
                    #pragma unroll
                    for (int m = 0; m < 2; ++m) {
                        float* c = C + m * 32 + q * 8 + hf * 4;
                        c[0] = bv.x; c[1] = bv.y; c[2] = bv.x; c[3] = bv.y;
                    }
                }
        }

        #pragma unroll
        for (int ks = 0; ks < 16; ++ks) {
            const uint32_t koff = (uint32_t)((ks & 7) * 32);
            uint32_t a0[4], a1[4], b[4][4];
            if (ks < 8) {
                ldsm4(aSI0 + koff, a0);
                ldsm4(aSI1 + koff, a1);
            } else {
                ldsm4(aSJ0 + koff, a0);
                ldsm4(aSJ1 + koff, a1);
            }
            #pragma unroll
            for (int q = 0; q < 4; ++q)
                ldsm4(bWE[q] + (uint32_t)(ks * 32), b[q]);
            #pragma unroll
            for (int q = 0; q < 4; ++q) {
                mma8(C + q * 8,          a0, b[q][0], b[q][1]);
                mma8(C + q * 8 + 4,      a0, b[q][2], b[q][3]);
                mma8(C + 32 + q * 8,     a1, b[q][0], b[q][1]);
                mma8(C + 32 + q * 8 + 4, a1, b[q][2], b[q][3]);
            }
        }
        __syncthreads();   // W_t / sj_t fully consumed

        // issue next loads (buffers free)
        if (t < 8) {
            int jn = (t + 1) + ((t + 1) >= i ? 1 : 0);
            cpblk(sb + SJ, g_s + (size_t)(jn * 8192 + b0) * S_S, TB * S_S, tid);
            cpblk(sb + WE, g_We + (size_t)(i * 9 + t + 1) * (128 * S_W), 128 * S_W, tid);
        } else {
            cpblk(sb + WN, g_WnA + (size_t)i * (64 * S_WNA), 64 * S_WNA, tid);
        }
        CP_COMMIT();

        // epilogue (overlaps in-flight cp.async + other CTA's MMAs)
        #pragma unroll
        for (int q = 0; q < 64; ++q) agg[q] += tanha(C[q]);
    }

    // ---- node phase: write agg as tf32 A-tile [64r][128h], rows of 528B ----
    #pragma unroll
    for (int q = 0; q < 4; ++q)
        #pragma unroll
        for (int hf = 0; hf < 2; ++hf) {
            int h = 64 * wn + 16 * q + 8 * hf + (lane & 3) * 2;
            #pragma unroll
            for (int m = 0; m < 2; ++m) {
                int idx = m * 32 + q * 8 + hf * 4;
                #pragma unroll
                for (int hh = 0; hh < 2; ++hh) {
                    int r = m0 + m * 16 + (lane >> 2) + 8 * hh;
                    uint2 w = { tf32c(agg[idx + 2 * hh]), tf32c(agg[idx + 2 * hh + 1]) };
                    *(uint2*)(smem + AGG + (uint32_t)(r * S_W) + (uint32_t)(h * 4)) = w;
                }
            }
        }
    CP_WAIT0();          // WnA staged
    __syncthreads();     // + AGG visible

    // node lane bases
    const uint32_t aACT0 = baseA(sb + ACT, m0,      S_A, lane);
    const uint32_t aACT1 = baseA(sb + ACT, m0 + 16, S_A, lane);
    const uint32_t aAG0  = baseA(sb + AGG, m0,      S_W, lane);
    const uint32_t aAG1  = baseA(sb + AGG, m0 + 16, S_W, lane);

    // init C2 from node bias: cols d = 32*wn + 16*q2 + 8*hf + 2*(lane&3)
    float C2[32];
    #pragma unroll
    for (int q2 = 0; q2 < 2; ++q2)
        #pragma unroll
        for (int hf = 0; hf < 2; ++hf) {
            int d = 32 * wn + 16 * q2 + 8 * hf + (lane & 3) * 2;
            float2 bn = *(const float2*)&b_node[(size_t)i * 64 + d];
            #pragma unroll
            for (int m = 0; m < 2; ++m) {
                float* c = C2 + m * 16 + q2 * 8 + hf * 4;
                c[0] = bn.x; c[1] = bn.y; c[2] = bn.x; c[3] = bn.y;
            }
        }

    // node GEMM: 26 k8-steps over F=208; WN chunkA = ks 0..13, chunkB = ks 14..25
    #pragma unroll
    for (int chunk = 0; chunk < 2; ++chunk) {
        const int S_WN = chunk ? S_WNB : S_WNA;
        uint32_t bWN[2];
        bWN[0] = baseB(sb + WN, 32 * wn,      S_WN, lane);
        bWN[1] = baseB(sb + WN, 32 * wn + 16, S_WN, lane);
        const int ksBeg = chunk ? 14 : 0;
        const int ksEnd = chunk ? 26 : 14;
        #pragma unroll
        for (int ks = ksBeg; ks < ksEnd; ++ks) {
            uint32_t a0[4], a1[4], bN[2][4];
            if (ks < 8) {
                ldsm4(aSI0 + (uint32_t)(ks * 32), a0);
                ldsm4(aSI1 + (uint32_t)(ks * 32), a1);
            } else if (ks < 10) {
                ldsm4(aACT0 + (uint32_t)((ks - 8) * 32), a0);
                ldsm4(aACT1 + (uint32_t)((ks - 8) * 32), a1);
            } else {
                ldsm4(aAG0 + (uint32_t)((ks - 10) * 32), a0);
                ldsm4(aAG1 + (uint32_t)((ks - 10) * 32), a1);
            }
            #pragma unroll
            for (int q2 = 0; q2 < 2; ++q2)
                ldsm4(bWN[q2] + (uint32_t)((ks - ksBeg) * 32), bN[q2]);
            #pragma unroll
            for (int q2 = 0; q2 < 2; ++q2) {
                mma8(C2 + q2 * 8,          a0, bN[q2][0], bN[q2][1]);
                mma8(C2 + q2 * 8 + 4,      a0, bN[q2][2], bN[q2][3]);
                mma8(C2 + 16 + q2 * 8,     a1, bN[q2][0], bN[q2][1]);
                mma8(C2 + 16 + q2 * 8 + 4, a1, bN[q2][2], bN[q2][3]);
            }
        }
        if (chunk == 0) {
            __syncthreads();   // WnA fully consumed
            cpblk(sb + WN, g_WnB + (size_t)i * (64 * S_WNB), 64 * S_WNB, tid);
            CP_COMMIT();
            CP_WAIT0();
            __syncthreads();   // WnB staged
        }
    }

    // ---- final epilogue: tanh + store ----
    #pragma unroll
    for (int q2 = 0; q2 < 2; ++q2)
        #pragma unroll
        for (int hf = 0; hf < 2; ++hf) {
            int d = 32 * wn + 16 * q2 + 8 * hf + (lane & 3) * 2;
            #pragma unroll
            for (int m = 0; m < 2; ++m) {
                int r0 = m0 + m * 16 + (lane >> 2);
                const float* c = C2 + m * 16 + q2 * 8 + hf * 4;
                float2 v0 = { tanha(c[0]), tanha(c[1]) };
                float2 v1 = { tanha(c[2]), tanha(c[3]) };
                *(float2*)&out[((size_t)(b0 + r0)     * KN + i) * 64 + d] = v0;
                *(float2*)&out[((size_t)(b0 + r0 + 8) * KN + i) * 64 + d] = v1;
            }
        }
}

extern "C" void kernel_launch(void* const* d_in, const int* in_sizes, int n_in,
                              void* d_out, int out_size)
{
    const float* states = (const float*)d_in[0];
    const float* action = (const float*)d_in[1];
    const float* W_edge = (const float*)d_in[2];
    const float* b_edge = (const float*)d_in[3];
    const float* W_node = (const float*)d_in[4];
    const float* b_node = (const float*)d_in[5];
    float* out = (float*)d_out;

    int B = in_sizes[0] / (KN * 64);   // 8192

    prep_kernel<<<2048, 256>>>(states, action, W_edge, W_node);

    cudaFuncSetAttribute(gnn_tf32_kernel,
                         cudaFuncAttributeMaxDynamicSharedMemorySize, SMEM_TOTAL);
    dim3 grid(B / TB, KN);
    gnn_tf32_kernel<<<grid, NT, SMEM_TOTAL>>>(b_edge, b_node, out);
}